// round 3
// baseline (speedup 1.0000x reference)
#include <cuda_runtime.h>
#include <cuda_bf16.h>
#include <cstddef>

// Per-edge cosine similarity + sigmoid + straight-through threshold.
// out[e] = let v = sigmoid(cos(f1,f2)/T) in (v <= 0.5 ? 0 : v)
//
// Layout: node_embs [N, 64] f32 (row = 16 float4), edge_index [2, E] i32,
// temperature scalar (dtype ambiguous: decode int-or-float bits).
//
// 8 lanes cooperate on one edge; each lane loads 2 float4 from each endpoint
// (256B per node row, coalesced, both 128B lines fully consumed), reduces
// dot/n1/n2 via shfl_xor. Node table (25.6 MB) is L2-resident -> the kernel
// is L2-bandwidth-bound (~1.02 GB of L2 reads).

static __device__ __forceinline__ float decode_scalar(const void* p) {
    if (p == nullptr) return 1.0f;
    int iv = *(const int*)p;
    // Small positive int => stored as int32. Otherwise an f32 bit pattern
    // (e.g. 1.0f = 0x3F800000, far above this range).
    if (iv > 0 && iv < (1 << 23)) return (float)iv;
    return __int_as_float(iv);
}

__global__ void __launch_bounds__(256) graph_cos_kernel(
    const float4* __restrict__ emb,   // [N*16] float4
    const int*    __restrict__ ei,    // [2*E]
    const void*   __restrict__ temp,  // scalar
    float*        __restrict__ out,   // [E]
    int E)
{
    int tid = blockIdx.x * blockDim.x + threadIdx.x;
    int eid = tid >> 3;          // 8 lanes per edge
    int sub = tid & 7;
    if (eid >= E) return;

    int i1 = __ldg(&ei[eid]);
    int i2 = __ldg(&ei[E + eid]);

    const float4* a = emb + (size_t)i1 * 16;
    const float4* b = emb + (size_t)i2 * 16;

    float4 a0 = __ldg(&a[sub]);
    float4 a1 = __ldg(&a[sub + 8]);
    float4 b0 = __ldg(&b[sub]);
    float4 b1 = __ldg(&b[sub + 8]);

    float dot = a0.x*b0.x + a0.y*b0.y + a0.z*b0.z + a0.w*b0.w
              + a1.x*b1.x + a1.y*b1.y + a1.z*b1.z + a1.w*b1.w;
    float n1  = a0.x*a0.x + a0.y*a0.y + a0.z*a0.z + a0.w*a0.w
              + a1.x*a1.x + a1.y*a1.y + a1.z*a1.z + a1.w*a1.w;
    float n2  = b0.x*b0.x + b0.y*b0.y + b0.z*b0.z + b0.w*b0.w
              + b1.x*b1.x + b1.y*b1.y + b1.z*b1.z + b1.w*b1.w;

    #pragma unroll
    for (int m = 4; m > 0; m >>= 1) {
        dot += __shfl_xor_sync(0xFFFFFFFFu, dot, m);
        n1  += __shfl_xor_sync(0xFFFFFFFFu, n1,  m);
        n2  += __shfl_xor_sync(0xFFFFFFFFu, n2,  m);
    }

    if (sub == 0) {
        const float eps = 1e-6f;
        float d1 = fmaxf(sqrtf(n1), eps);
        float d2 = fmaxf(sqrtf(n2), eps);
        float att = dot / (d1 * d2);
        float T = decode_scalar(temp);
        float v = 1.0f / (1.0f + __expf(-att / T));
        out[eid] = (v <= 0.5f) ? 0.0f : v;
    }
}

extern "C" void kernel_launch(void* const* d_in, const int* in_sizes, int n_in,
                              void* d_out, int out_size)
{
    const float4* emb  = (const float4*)d_in[0];
    const int*    ei   = (const int*)d_in[1];
    const void*   temp = (n_in > 2) ? d_in[2] : nullptr;
    float*        out  = (float*)d_out;

    int E = in_sizes[1] / 2;   // edge_index has 2*E elements

    int threads = 256;
    long long total = (long long)E * 8;
    int blocks = (int)((total + threads - 1) / threads);
    graph_cos_kernel<<<blocks, threads>>>(emb, ei, temp, out, E);
}